// round 6
// baseline (speedup 1.0000x reference)
#include <cuda_runtime.h>
#include <cuda_fp16.h>

// GCN_56882546868697 — R6: divergence-free warp-per-node aggregation,
// dual-stream split binning, fork-at-zero init.

#define NN 100000
#define NE 1600000
#define DF 64
#define LT 64
#define NC 16
#define NEG 0.01f

// ---- static scratch ----
__device__ __align__(16) __half g_h[NN * LT];  // layer-1 pre-agg, fp16 (128B/row)
__device__ __align__(16) __half g_z[NN * NC];  // layer-2 sigmoid acts, fp16 (32B/row)
__device__ int g_degs[NN];
__device__ int g_degr[NN];
__device__ int g_beg[NN];
__device__ int g_cur[NN];
__device__ int g_csr[NE];
__device__ int g_total;

// ---------------------------------------------------------------- init (split per branch)
__global__ void k_init_r(int nn) {
    const int stride = gridDim.x * blockDim.x;
    int t0 = blockIdx.x * blockDim.x + threadIdx.x;
    for (int i = t0; i < nn; i += stride) g_degr[i] = 0;
    if (t0 == 0) g_total = 0;
}
__global__ void k_init_s(int nn) {
    const int stride = gridDim.x * blockDim.x;
    for (int i = blockIdx.x * blockDim.x + threadIdx.x; i < nn; i += stride) g_degs[i] = 0;
}

// ---------------------------------------------------------------- degree histograms
__global__ void k_hist_s(const int* __restrict__ senders, int ne) {
    int t = blockIdx.x * blockDim.x + threadIdx.x;
    int e0 = t * 4;
    if (e0 + 3 < ne) {
        int4 s = *reinterpret_cast<const int4*>(&senders[e0]);
        atomicAdd(&g_degs[s.x], 1); atomicAdd(&g_degs[s.y], 1);
        atomicAdd(&g_degs[s.z], 1); atomicAdd(&g_degs[s.w], 1);
    } else {
        for (int e = e0; e < ne; ++e) atomicAdd(&g_degs[__ldg(&senders[e])], 1);
    }
}
__global__ void k_hist_r(const int* __restrict__ receivers, int ne) {
    int t = blockIdx.x * blockDim.x + threadIdx.x;
    int e0 = t * 4;
    if (e0 + 3 < ne) {
        int4 r = *reinterpret_cast<const int4*>(&receivers[e0]);
        atomicAdd(&g_degr[r.x], 1); atomicAdd(&g_degr[r.y], 1);
        atomicAdd(&g_degr[r.z], 1); atomicAdd(&g_degr[r.w], 1);
    } else {
        for (int e = e0; e < ne; ++e) atomicAdd(&g_degr[__ldg(&receivers[e])], 1);
    }
}

// ---------------------------------------------------------------- segment offsets (warp scan)
__global__ void k_offsets(int nn) {
    int i = blockIdx.x * blockDim.x + threadIdx.x;
    int lane = threadIdx.x & 31;
    int d = (i < nn) ? g_degr[i] : 0;
    int pre = d;
#pragma unroll
    for (int o = 1; o < 32; o <<= 1) {
        int v = __shfl_up_sync(0xffffffffu, pre, o);
        if (lane >= o) pre += v;
    }
    int excl = pre - d;
    int wsum = __shfl_sync(0xffffffffu, pre, 31);
    int base = 0;
    if (lane == 0) base = atomicAdd(&g_total, wsum);
    base = __shfl_sync(0xffffffffu, base, 0);
    if (i < nn) {
        int b = base + excl;
        g_beg[i] = b;
        g_cur[i] = b;
    }
}

// ---------------------------------------------------------------- bin (runs concurrently on 2 streams)
__global__ void k_bin(const int* __restrict__ senders,
                      const int* __restrict__ receivers, int ne) {
    int t = blockIdx.x * blockDim.x + threadIdx.x;
    int e0 = t * 4;
    if (e0 + 3 < ne) {
        int4 s = *reinterpret_cast<const int4*>(&senders[e0]);
        int4 r = *reinterpret_cast<const int4*>(&receivers[e0]);
        int p0 = atomicAdd(&g_cur[r.x], 1);
        int p1 = atomicAdd(&g_cur[r.y], 1);
        int p2 = atomicAdd(&g_cur[r.z], 1);
        int p3 = atomicAdd(&g_cur[r.w], 1);
        g_csr[p0] = s.x; g_csr[p1] = s.y; g_csr[p2] = s.z; g_csr[p3] = s.w;
    } else {
        for (int e = e0; e < ne; ++e) {
            int r = __ldg(&receivers[e]);
            g_csr[atomicAdd(&g_cur[r], 1)] = __ldg(&senders[e]);
        }
    }
}

// ---------------------------------------------------------------- GEMM1 + sender norm -> fp16
__global__ void k_gemm1(const float* __restrict__ nodes,
                        const float* __restrict__ W0,
                        const float* __restrict__ b0, int nn) {
    __shared__ __align__(16) float sW[DF * LT];
    __shared__ float sx[64][DF + 1];
    const int tid = threadIdx.x;
    const int row0 = blockIdx.x * 64;

    for (int i = tid; i < DF * LT; i += 256) sW[i] = W0[i];
    for (int idx = tid; idx < 64 * 16; idx += 256) {
        int r = idx >> 4, k0 = (idx & 15) * 4;
        int grow = row0 + r;
        float4 v = (grow < nn)
            ? *reinterpret_cast<const float4*>(&nodes[grow * DF + k0])
            : make_float4(0.f, 0.f, 0.f, 0.f);
        sx[r][k0] = v.x; sx[r][k0 + 1] = v.y; sx[r][k0 + 2] = v.z; sx[r][k0 + 3] = v.w;
    }
    __syncthreads();

    const int ty = tid >> 4, tx = tid & 15;
    const int r0 = ty * 4, c0 = tx * 4;

    unsigned long long acc[4][2];
#pragma unroll
    for (int i = 0; i < 4; ++i) { acc[i][0] = 0ull; acc[i][1] = 0ull; }

#pragma unroll
    for (int k = 0; k < DF; ++k) {
        ulonglong2 b2 = *reinterpret_cast<const ulonglong2*>(&sW[k * LT + c0]);
#pragma unroll
        for (int i = 0; i < 4; ++i) {
            float a = sx[r0 + i][k];
            unsigned long long ap;
            asm("mov.b64 %0, {%1, %1};" : "=l"(ap) : "r"(__float_as_uint(a)));
            asm("fma.rn.f32x2 %0, %1, %2, %0;" : "+l"(acc[i][0]) : "l"(ap), "l"(b2.x));
            asm("fma.rn.f32x2 %0, %1, %2, %0;" : "+l"(acc[i][1]) : "l"(ap), "l"(b2.y));
        }
    }

    const float4 bias = *reinterpret_cast<const float4*>(&b0[c0]);
#pragma unroll
    for (int i = 0; i < 4; ++i) {
        int grow = row0 + r0 + i;
        if (grow < nn) {
            unsigned lo0, hi0, lo1, hi1;
            asm("mov.b64 {%0, %1}, %2;" : "=r"(lo0), "=r"(hi0) : "l"(acc[i][0]));
            asm("mov.b64 {%0, %1}, %2;" : "=r"(lo1), "=r"(hi1) : "l"(acc[i][1]));
            float s = rsqrtf(fmaxf((float)g_degs[grow], 1.0f));
            float ox = (__uint_as_float(lo0) + bias.x) * s;
            float oy = (__uint_as_float(hi0) + bias.y) * s;
            float oz = (__uint_as_float(lo1) + bias.z) * s;
            float ow = (__uint_as_float(hi1) + bias.w) * s;
            __half2 h0 = __floats2half2_rn(ox, oy);
            __half2 h1 = __floats2half2_rn(oz, ow);
            uint2 st;
            st.x = *reinterpret_cast<unsigned*>(&h0);
            st.y = *reinterpret_cast<unsigned*>(&h1);
            *reinterpret_cast<uint2*>(&g_h[grow * LT + c0]) = st;
        }
    }
}

// ---------------------------------------------------------------- agg1 + norm + leaky + GEMM2 + sigmoid
// One warp per node: lane l owns halves [2l, 2l+1] of the 128B row -> zero
// intra-warp divergence, fully coalesced 128B gathers. 256 thr = 8 nodes.
__global__ void k_agg1l2(const float* __restrict__ W1,
                         const float* __restrict__ b1, int nn) {
    __shared__ float sW1[LT * NC];        // [k][c]
    __shared__ float sact[8][LT + 2];
    const int tid = threadIdx.x;
    for (int i = tid; i < LT * NC; i += 256) sW1[i] = W1[i];

    const int wid = tid >> 5;
    const int lane = tid & 31;
    const int node = blockIdx.x * 8 + wid;

    if (node < nn) {
        int beg = g_beg[node];
        int deg = g_degr[node];
        int end = beg + deg;
        float a0 = 0.f, a1 = 0.f;
        int i = beg;
        for (; i + 4 <= end; i += 4) {
            int s0 = __ldg(&g_csr[i]);
            int s1 = __ldg(&g_csr[i + 1]);
            int s2 = __ldg(&g_csr[i + 2]);
            int s3 = __ldg(&g_csr[i + 3]);
            unsigned u0 = *reinterpret_cast<const unsigned*>(&g_h[s0 * LT + lane * 2]);
            unsigned u1 = *reinterpret_cast<const unsigned*>(&g_h[s1 * LT + lane * 2]);
            unsigned u2 = *reinterpret_cast<const unsigned*>(&g_h[s2 * LT + lane * 2]);
            unsigned u3 = *reinterpret_cast<const unsigned*>(&g_h[s3 * LT + lane * 2]);
            float2 f0 = __half22float2(*reinterpret_cast<__half2*>(&u0));
            float2 f1 = __half22float2(*reinterpret_cast<__half2*>(&u1));
            float2 f2 = __half22float2(*reinterpret_cast<__half2*>(&u2));
            float2 f3 = __half22float2(*reinterpret_cast<__half2*>(&u3));
            a0 += f0.x + f1.x + f2.x + f3.x;
            a1 += f0.y + f1.y + f2.y + f3.y;
        }
        for (; i < end; ++i) {
            int s = __ldg(&g_csr[i]);
            unsigned u = *reinterpret_cast<const unsigned*>(&g_h[s * LT + lane * 2]);
            float2 f = __half22float2(*reinterpret_cast<__half2*>(&u));
            a0 += f.x; a1 += f.y;
        }
        float dr = rsqrtf(fmaxf((float)deg, 1.0f));
        a0 *= dr; a1 *= dr;
        a0 = (a0 >= 0.f) ? a0 : NEG * a0;
        a1 = (a1 >= 0.f) ? a1 : NEG * a1;
        sact[wid][lane * 2]     = a0;
        sact[wid][lane * 2 + 1] = a1;
    }
    __syncthreads();

    // GEMM2: 128 threads = 8 nodes x 16 out-cols
    if (tid < 128) {
        int ln = tid >> 4, c = tid & 15;
        int node2 = blockIdx.x * 8 + ln;
        if (node2 < nn) {
            float acc = __ldg(&b1[c]);
#pragma unroll
            for (int k = 0; k < LT; ++k) acc += sact[ln][k] * sW1[k * NC + c];
            float zz = 1.0f / (1.0f + __expf(-acc));
            g_z[node2 * NC + c] = __float2half_rn(zz);
        }
    }
}

// ---------------------------------------------------------------- agg2: warp per node
// lanes = 4 edge-slots x 8 cols; shfl-reduce over slots; lanes<8 write 64B row.
__global__ void k_agg2(float* __restrict__ out, int nn) {
    const int tid = threadIdx.x;
    const int wid = tid >> 5;
    const int lane = tid & 31;
    const int node = blockIdx.x * 8 + wid;
    if (node >= nn) return;
    const int eslot = lane >> 3;   // 0..3
    const int col = lane & 7;      // 0..7
    int beg = g_beg[node];
    int end = beg + g_degr[node];
    float ax = 0.f, ay = 0.f;
    int i = beg + eslot;
    for (; i + 4 < end; i += 8) {
        int s0 = __ldg(&g_csr[i]);
        int s1 = __ldg(&g_csr[i + 4]);
        unsigned u0 = *reinterpret_cast<const unsigned*>(&g_z[s0 * NC + col * 2]);
        unsigned u1 = *reinterpret_cast<const unsigned*>(&g_z[s1 * NC + col * 2]);
        float2 f0 = __half22float2(*reinterpret_cast<__half2*>(&u0));
        float2 f1 = __half22float2(*reinterpret_cast<__half2*>(&u1));
        ax += f0.x + f1.x; ay += f0.y + f1.y;
    }
    if (i < end) {
        int s = __ldg(&g_csr[i]);
        unsigned u = *reinterpret_cast<const unsigned*>(&g_z[s * NC + col * 2]);
        float2 f = __half22float2(*reinterpret_cast<__half2*>(&u));
        ax += f.x; ay += f.y;
    }
    ax += __shfl_xor_sync(0xffffffffu, ax, 8);
    ay += __shfl_xor_sync(0xffffffffu, ay, 8);
    ax += __shfl_xor_sync(0xffffffffu, ax, 16);
    ay += __shfl_xor_sync(0xffffffffu, ay, 16);
    if (lane < 8) {
        float2 o; o.x = ax; o.y = ay;
        *reinterpret_cast<float2*>(&out[node * NC + col * 2]) = o;
    }
}

// ---------------------------------------------------------------- launch (fork/join, split bin)
extern "C" void kernel_launch(void* const* d_in, const int* in_sizes, int n_in,
                              void* d_out, int out_size) {
    const float* nodes     = (const float*)d_in[0];
    const int*   senders   = (const int*)  d_in[1];
    const int*   receivers = (const int*)  d_in[2];
    const float* W0        = (const float*)d_in[3];
    const float* b0        = (const float*)d_in[4];
    const float* W1        = (const float*)d_in[5];
    const float* b1        = (const float*)d_in[6];
    float*       out       = (float*)d_out;

    const int nn = in_sizes[0] / DF;       // 100000
    const int ne = in_sizes[1];            // 1600000
    const int eg = ((ne + 3) / 4 + 255) / 256;

    // edge split for concurrent binning (int4-aligned)
    const int ne_lo = ((ne / 2) + 3) & ~3;
    const int ne_hi = ne - ne_lo;
    const int eg_lo = ((ne_lo + 3) / 4 + 255) / 256;
    const int eg_hi = ((ne_hi + 3) / 4 + 255) / 256;

    static cudaStream_t s2 = 0;
    static cudaEvent_t evFork = 0, evOff = 0, evJoin = 0;
    if (!s2) {
        cudaStreamCreateWithFlags(&s2, cudaStreamNonBlocking);
        cudaEventCreateWithFlags(&evFork, cudaEventDisableTiming);
        cudaEventCreateWithFlags(&evOff, cudaEventDisableTiming);
        cudaEventCreateWithFlags(&evJoin, cudaEventDisableTiming);
    }

    // fork at t=0
    cudaEventRecord(evFork, 0);
    cudaStreamWaitEvent(s2, evFork, 0);

    // branch B (s2): init degs -> hist_s -> GEMM1 -> (after offsets) bin_hi
    k_init_s<<<128, 256, 0, s2>>>(nn);
    k_hist_s<<<eg, 256, 0, s2>>>(senders, ne);
    k_gemm1<<<(nn + 63) / 64, 256, 0, s2>>>(nodes, W0, b0, nn);

    // branch A (s0): init degr -> hist_r -> offsets -> bin_lo
    k_init_r<<<128, 256>>>(nn);
    k_hist_r<<<eg, 256>>>(receivers, ne);
    k_offsets<<<(nn + 255) / 256, 256>>>(nn);
    cudaEventRecord(evOff, 0);

    cudaStreamWaitEvent(s2, evOff, 0);
    k_bin<<<eg_hi, 256, 0, s2>>>(senders + ne_lo, receivers + ne_lo, ne_hi);
    cudaEventRecord(evJoin, s2);

    k_bin<<<eg_lo, 256>>>(senders, receivers, ne_lo);

    // join: aggregation needs CSR halves + g_h
    cudaStreamWaitEvent(0, evJoin, 0);
    k_agg1l2<<<(nn + 7) / 8, 256>>>(W1, b1, nn);
    k_agg2<<<(nn + 7) / 8, 256>>>(out, nn);
}